// round 1
// baseline (speedup 1.0000x reference)
#include <cuda_runtime.h>

#define BB 4
#define CC 64
#define NN 9216          // 96*96
#define NT 144           // NN/64
#define EPSN 1e-5f

// -------- scratch (device globals; no allocation allowed) --------
__device__ float g_mean[BB*CC];
__device__ float g_rstd[BB*CC];
__device__ float g_q[BB*CC*NN];   // [b][c][n]
__device__ float g_k[BB*CC*NN];   // [b][c][n]
__device__ float g_v[BB*NN*CC];   // [b][n][c]
__device__ float g_o[BB*NN*CC];   // [b][n][c]

// ============================================================
// Kernel A: per-(b,c) instance-norm statistics
// ============================================================
__global__ __launch_bounds__(256) void norm_stats(const float* __restrict__ x)
{
    int bc = blockIdx.x;                 // 0..BB*CC-1
    const float* p = x + (size_t)bc * NN;
    float s = 0.f, ss = 0.f;
    for (int i = threadIdx.x; i < NN; i += 256) {
        float v = p[i];
        s += v; ss += v * v;
    }
    __shared__ float sh[16];
#pragma unroll
    for (int o = 16; o >= 1; o >>= 1) {
        s  += __shfl_xor_sync(0xffffffffu, s,  o);
        ss += __shfl_xor_sync(0xffffffffu, ss, o);
    }
    int w = threadIdx.x >> 5, l = threadIdx.x & 31;
    if (l == 0) { sh[w] = s; sh[w + 8] = ss; }
    __syncthreads();
    if (threadIdx.x == 0) {
        float S = 0.f, SS = 0.f;
#pragma unroll
        for (int i = 0; i < 8; i++) { S += sh[i]; SS += sh[i + 8]; }
        float mean = S / (float)NN;
        float var  = SS / (float)NN - mean * mean;
        g_mean[bc] = mean;
        g_rstd[bc] = rsqrtf(var + EPSN);
    }
}

// ============================================================
// Kernel B: fused instance-norm apply + Q/K/V 1x1 convs
//   q,k -> [b][c][n],  v -> [b][n][c]
// ============================================================
__global__ __launch_bounds__(256) void qkv_kernel(
    const float* __restrict__ x,
    const float* __restrict__ wq, const float* __restrict__ bq,
    const float* __restrict__ wk, const float* __restrict__ bk,
    const float* __restrict__ wv, const float* __restrict__ bv)
{
    __shared__ float h_s[64][68];   // [c][n]
    __shared__ float w_s[64][68];   // [c][o]  (W transposed)
    int b  = blockIdx.y;
    int n0 = blockIdx.x * 64;
    int t  = threadIdx.x;
    int tx = t & 15, ty = t >> 4;

    const float* xb = x + (size_t)(b * 64) * NN;
#pragma unroll
    for (int p = 0; p < 4; p++) {
        int c   = (t >> 4) + p * 16;
        int col = (t & 15) * 4;
        float4 v = *(const float4*)(xb + c * NN + n0 + col);
        float mean = g_mean[b * 64 + c], rstd = g_rstd[b * 64 + c];
        float4 hv = make_float4((v.x - mean) * rstd, (v.y - mean) * rstd,
                                (v.z - mean) * rstd, (v.w - mean) * rstd);
        *(float4*)&h_s[c][col] = hv;
    }

    for (int mi = 0; mi < 3; mi++) {
        const float* W  = (mi == 0) ? wq : ((mi == 1) ? wk : wv);
        const float* Bv = (mi == 0) ? bq : ((mi == 1) ? bk : bv);
        __syncthreads();   // prior GEMM done with w_s (also orders first h_s use)
#pragma unroll
        for (int p = 0; p < 4; p++) {
            int o  = (t >> 4) + p * 16;
            int c4 = (t & 15) * 4;
            float4 v = *(const float4*)(W + o * 64 + c4);
            w_s[c4 + 0][o] = v.x; w_s[c4 + 1][o] = v.y;
            w_s[c4 + 2][o] = v.z; w_s[c4 + 3][o] = v.w;
        }
        __syncthreads();

        float acc[4][4] = {};
#pragma unroll 8
        for (int c = 0; c < 64; c++) {
            float4 w4 = *(float4*)&w_s[c][ty * 4];
            float4 h4 = *(float4*)&h_s[c][tx * 4];
            float wa[4] = {w4.x, w4.y, w4.z, w4.w};
            float ha[4] = {h4.x, h4.y, h4.z, h4.w};
#pragma unroll
            for (int ii = 0; ii < 4; ii++)
#pragma unroll
                for (int jj = 0; jj < 4; jj++)
                    acc[ii][jj] += wa[ii] * ha[jj];
        }
        float bias[4];
#pragma unroll
        for (int ii = 0; ii < 4; ii++) bias[ii] = Bv[ty * 4 + ii];

        if (mi < 2) {
            float* out = (mi == 0 ? g_q : g_k) + (size_t)(b * 64) * NN;
#pragma unroll
            for (int ii = 0; ii < 4; ii++) {
                float4 r = make_float4(acc[ii][0] + bias[ii], acc[ii][1] + bias[ii],
                                       acc[ii][2] + bias[ii], acc[ii][3] + bias[ii]);
                *(float4*)(out + (ty * 4 + ii) * NN + n0 + tx * 4) = r;
            }
        } else {
            float* out = g_v + (size_t)(b * NN + n0) * 64;
#pragma unroll
            for (int jj = 0; jj < 4; jj++) {
                float4 r = make_float4(acc[0][jj] + bias[0], acc[1][jj] + bias[1],
                                       acc[2][jj] + bias[2], acc[3][jj] + bias[3]);
                *(float4*)(out + (tx * 4 + jj) * 64 + ty * 4) = r;
            }
        }
    }
}

// ============================================================
// Kernel C: flash attention, 64x64 tiles, fp32 register tiling
// ============================================================
__global__ __launch_bounds__(256) void flash_kernel()
{
    extern __shared__ float smem[];
    float* Qs = smem;                 // [c][i]  (Q^T, pre-scaled)
    float* Ks = smem + 64 * 68;       // [c][j]
    float* Vs = smem + 2 * 64 * 68;   // [m][c]
    float* Ps = smem + 3 * 64 * 68;   // [i][m]

    int b  = blockIdx.y;
    int n0 = blockIdx.x * 64;
    int t  = threadIdx.x;
    int tx = t & 15, ty = t >> 4;
    const float scale = 0.125f;       // C^-0.5, C=64

#pragma unroll
    for (int p = 0; p < 4; p++) {
        int c  = (t >> 4) + p * 16;
        int i4 = (t & 15) * 4;
        float4 v = *(const float4*)(g_q + (size_t)(b * 64 + c) * NN + n0 + i4);
        v.x *= scale; v.y *= scale; v.z *= scale; v.w *= scale;
        *(float4*)&Qs[c * 68 + i4] = v;
    }

    float m_i[4], l_i[4], oacc[4][4];
#pragma unroll
    for (int ii = 0; ii < 4; ii++) {
        m_i[ii] = -1e30f; l_i[ii] = 0.f;
#pragma unroll
        for (int jj = 0; jj < 4; jj++) oacc[ii][jj] = 0.f;
    }

    for (int kt = 0; kt < NT; kt++) {
        int m0 = kt * 64;
        __syncthreads();   // prior iteration done reading Vs/Ps (also orders Qs on kt==0)
#pragma unroll
        for (int p = 0; p < 4; p++) {
            int r  = (t >> 4) + p * 16;
            int c4 = (t & 15) * 4;
            *(float4*)&Ks[r * 68 + c4] =
                *(const float4*)(g_k + (size_t)(b * 64 + r) * NN + m0 + c4);
            *(float4*)&Vs[r * 68 + c4] =
                *(const float4*)(g_v + (size_t)(b * NN + m0 + r) * 64 + c4);
        }
        __syncthreads();

        // S = (Q^T)^T K : 4x4 microtile per thread
        float s[4][4] = {};
#pragma unroll 8
        for (int c = 0; c < 64; c++) {
            float4 q4 = *(float4*)&Qs[c * 68 + ty * 4];
            float4 k4 = *(float4*)&Ks[c * 68 + tx * 4];
            float qa[4] = {q4.x, q4.y, q4.z, q4.w};
            float ka[4] = {k4.x, k4.y, k4.z, k4.w};
#pragma unroll
            for (int ii = 0; ii < 4; ii++)
#pragma unroll
                for (int jj = 0; jj < 4; jj++)
                    s[ii][jj] += qa[ii] * ka[jj];
        }

        // online softmax, row reductions over the 16 tx lanes
#pragma unroll
        for (int ii = 0; ii < 4; ii++) {
            float tm = fmaxf(fmaxf(s[ii][0], s[ii][1]), fmaxf(s[ii][2], s[ii][3]));
#pragma unroll
            for (int off = 8; off >= 1; off >>= 1)
                tm = fmaxf(tm, __shfl_xor_sync(0xffffffffu, tm, off, 16));
            float mn   = fmaxf(m_i[ii], tm);
            float corr = __expf(m_i[ii] - mn);
            m_i[ii] = mn;
            float rs = 0.f;
#pragma unroll
            for (int jj = 0; jj < 4; jj++) {
                s[ii][jj] = __expf(s[ii][jj] - mn);
                rs += s[ii][jj];
            }
#pragma unroll
            for (int off = 8; off >= 1; off >>= 1)
                rs += __shfl_xor_sync(0xffffffffu, rs, off, 16);
            l_i[ii] = l_i[ii] * corr + rs;
#pragma unroll
            for (int jj = 0; jj < 4; jj++) oacc[ii][jj] *= corr;
            *(float4*)&Ps[(ty * 4 + ii) * 68 + tx * 4] =
                make_float4(s[ii][0], s[ii][1], s[ii][2], s[ii][3]);
        }
        __syncthreads();

        // O += P V
#pragma unroll 8
        for (int m = 0; m < 64; m++) {
            float4 v4 = *(float4*)&Vs[m * 68 + tx * 4];
            float p0 = Ps[(ty * 4 + 0) * 68 + m];
            float p1 = Ps[(ty * 4 + 1) * 68 + m];
            float p2 = Ps[(ty * 4 + 2) * 68 + m];
            float p3 = Ps[(ty * 4 + 3) * 68 + m];
            oacc[0][0] += p0 * v4.x; oacc[0][1] += p0 * v4.y; oacc[0][2] += p0 * v4.z; oacc[0][3] += p0 * v4.w;
            oacc[1][0] += p1 * v4.x; oacc[1][1] += p1 * v4.y; oacc[1][2] += p1 * v4.z; oacc[1][3] += p1 * v4.w;
            oacc[2][0] += p2 * v4.x; oacc[2][1] += p2 * v4.y; oacc[2][2] += p2 * v4.z; oacc[2][3] += p2 * v4.w;
            oacc[3][0] += p3 * v4.x; oacc[3][1] += p3 * v4.y; oacc[3][2] += p3 * v4.z; oacc[3][3] += p3 * v4.w;
        }
    }

#pragma unroll
    for (int ii = 0; ii < 4; ii++) {
        float inv = 1.f / l_i[ii];
        float4 r = make_float4(oacc[ii][0] * inv, oacc[ii][1] * inv,
                               oacc[ii][2] * inv, oacc[ii][3] * inv);
        *(float4*)(g_o + (size_t)(b * NN + n0 + ty * 4 + ii) * 64 + tx * 4) = r;
    }
}

// ============================================================
// Kernel D: output 1x1 conv + bias + residual
// ============================================================
__global__ __launch_bounds__(256) void proj_kernel(
    const float* __restrict__ x,
    const float* __restrict__ wo, const float* __restrict__ bo,
    float* __restrict__ out)
{
    __shared__ float A_s[64][68];   // [c][n]  (attn out transposed)
    __shared__ float Wt[64][68];    // [c][o]
    int b  = blockIdx.y;
    int n0 = blockIdx.x * 64;
    int t  = threadIdx.x;
    int tx = t & 15, ty = t >> 4;

#pragma unroll
    for (int p = 0; p < 4; p++) {
        int i  = (t >> 4) + p * 16;
        int c4 = (t & 15) * 4;
        float4 v = *(const float4*)(g_o + (size_t)(b * NN + n0 + i) * 64 + c4);
        A_s[c4 + 0][i] = v.x; A_s[c4 + 1][i] = v.y;
        A_s[c4 + 2][i] = v.z; A_s[c4 + 3][i] = v.w;
        float4 w = *(const float4*)(wo + i * 64 + c4);
        Wt[c4 + 0][i] = w.x; Wt[c4 + 1][i] = w.y;
        Wt[c4 + 2][i] = w.z; Wt[c4 + 3][i] = w.w;
    }
    __syncthreads();

    float acc[4][4] = {};
#pragma unroll 8
    for (int c = 0; c < 64; c++) {
        float4 w4 = *(float4*)&Wt[c][ty * 4];
        float4 a4 = *(float4*)&A_s[c][tx * 4];
        float wa[4] = {w4.x, w4.y, w4.z, w4.w};
        float aa[4] = {a4.x, a4.y, a4.z, a4.w};
#pragma unroll
        for (int ii = 0; ii < 4; ii++)
#pragma unroll
            for (int jj = 0; jj < 4; jj++)
                acc[ii][jj] += wa[ii] * aa[jj];
    }

#pragma unroll
    for (int ii = 0; ii < 4; ii++) {
        int o = ty * 4 + ii;
        float bias = bo[o];
        const float4 xv = *(const float4*)(x + (size_t)(b * 64 + o) * NN + n0 + tx * 4);
        float4 r = make_float4(xv.x + bias + acc[ii][0], xv.y + bias + acc[ii][1],
                               xv.z + bias + acc[ii][2], xv.w + bias + acc[ii][3]);
        *(float4*)(out + (size_t)(b * 64 + o) * NN + n0 + tx * 4) = r;
    }
}

// ============================================================
extern "C" void kernel_launch(void* const* d_in, const int* in_sizes, int n_in,
                              void* d_out, int out_size)
{
    const float* x  = (const float*)d_in[0];
    const float* wq = (const float*)d_in[1];
    const float* bq = (const float*)d_in[2];
    const float* wk = (const float*)d_in[3];
    const float* bk = (const float*)d_in[4];
    const float* wv = (const float*)d_in[5];
    const float* bv = (const float*)d_in[6];
    const float* wo = (const float*)d_in[7];
    const float* bo = (const float*)d_in[8];
    float* out = (float*)d_out;

    cudaFuncSetAttribute(flash_kernel, cudaFuncAttributeMaxDynamicSharedMemorySize,
                         4 * 64 * 68 * (int)sizeof(float));

    norm_stats<<<BB * CC, 256>>>(x);
    qkv_kernel<<<dim3(NT, BB), 256>>>(x, wq, bq, wk, bk, wv, bv);
    flash_kernel<<<dim3(NT, BB), 256, 4 * 64 * 68 * sizeof(float)>>>();
    proj_kernel<<<dim3(NT, BB), 256>>>(x, wo, bo, out);
}

// round 3
// speedup vs baseline: 3.3774x; 3.3774x over previous
#include <cuda_runtime.h>

#define BB 4
#define CC 64
#define NN 9216          // 96*96
#define EPSN 1e-5f

#define BM 128           // queries per CTA (8 warps x 16 rows)
#define BN 64            // keys per iteration
#define NKT (NN / BN)    // 144 key tiles
#define NQB (NN / BM)    // 72 query blocks

// smem strides (words) chosen for conflict-free fragment loads
#define KS_STRIDE 68     // bank = 4g+tig  (distinct)
#define VS_STRIDE 72     // bank = 8tig+g  (distinct)
#define PS_STRIDE 68

#define SMEM_FLASH ((BN * KS_STRIDE + BN * VS_STRIDE + BM * PS_STRIDE) * 4)

// -------- scratch (device globals; no allocation allowed) --------
__device__ float g_mean[BB*CC];
__device__ float g_rstd[BB*CC];
__device__ float g_q[BB*NN*CC];   // [b][n][c]
__device__ float g_k[BB*NN*CC];   // [b][n][c]
__device__ float g_v[BB*NN*CC];   // [b][n][c]
__device__ float g_o[BB*NN*CC];   // [b][n][c]

__device__ __forceinline__ float to_tf32(float x) {
    float r;
    asm("cvt.rna.tf32.f32 %0, %1;" : "=f"(r) : "f"(x));
    return r;
}

__device__ __forceinline__ void mma8(float* c, const unsigned* a, unsigned b0, unsigned b1) {
    asm volatile(
        "mma.sync.aligned.m16n8k8.row.col.f32.tf32.tf32.f32 "
        "{%0,%1,%2,%3},{%4,%5,%6,%7},{%8,%9},{%0,%1,%2,%3};"
        : "+f"(c[0]), "+f"(c[1]), "+f"(c[2]), "+f"(c[3])
        : "r"(a[0]), "r"(a[1]), "r"(a[2]), "r"(a[3]), "r"(b0), "r"(b1));
}

// ============================================================
// Kernel A: per-(b,c) instance-norm statistics
// ============================================================
__global__ __launch_bounds__(256) void norm_stats(const float* __restrict__ x)
{
    int bc = blockIdx.x;
    const float* p = x + (size_t)bc * NN;
    float s = 0.f, ss = 0.f;
    for (int i = threadIdx.x; i < NN; i += 256) {
        float v = p[i];
        s += v; ss += v * v;
    }
    __shared__ float sh[16];
#pragma unroll
    for (int o = 16; o >= 1; o >>= 1) {
        s  += __shfl_xor_sync(0xffffffffu, s,  o);
        ss += __shfl_xor_sync(0xffffffffu, ss, o);
    }
    int w = threadIdx.x >> 5, l = threadIdx.x & 31;
    if (l == 0) { sh[w] = s; sh[w + 8] = ss; }
    __syncthreads();
    if (threadIdx.x == 0) {
        float S = 0.f, SS = 0.f;
#pragma unroll
        for (int i = 0; i < 8; i++) { S += sh[i]; SS += sh[i + 8]; }
        float mean = S / (float)NN;
        float var  = SS / (float)NN - mean * mean;
        g_mean[bc] = mean;
        g_rstd[bc] = rsqrtf(var + EPSN);
    }
}

// ============================================================
// Kernel B: fused instance-norm apply + Q/K/V 1x1 convs
//   all outputs in [b][n][c] layout
// ============================================================
__global__ __launch_bounds__(256) void qkv_kernel(
    const float* __restrict__ x,
    const float* __restrict__ wq, const float* __restrict__ bq,
    const float* __restrict__ wk, const float* __restrict__ bk,
    const float* __restrict__ wv, const float* __restrict__ bv)
{
    __shared__ float h_s[64][68];   // [c][n]
    __shared__ float w_s[64][68];   // [c][o]
    int b  = blockIdx.y;
    int n0 = blockIdx.x * 64;
    int t  = threadIdx.x;
    int tx = t & 15, ty = t >> 4;

    const float* xb = x + (size_t)(b * 64) * NN;
#pragma unroll
    for (int p = 0; p < 4; p++) {
        int c   = (t >> 4) + p * 16;
        int col = (t & 15) * 4;
        float4 v = *(const float4*)(xb + c * NN + n0 + col);
        float mean = g_mean[b * 64 + c], rstd = g_rstd[b * 64 + c];
        float4 hv = make_float4((v.x - mean) * rstd, (v.y - mean) * rstd,
                                (v.z - mean) * rstd, (v.w - mean) * rstd);
        *(float4*)&h_s[c][col] = hv;
    }

    for (int mi = 0; mi < 3; mi++) {
        const float* W  = (mi == 0) ? wq : ((mi == 1) ? wk : wv);
        const float* Bv = (mi == 0) ? bq : ((mi == 1) ? bk : bv);
        __syncthreads();
#pragma unroll
        for (int p = 0; p < 4; p++) {
            int o  = (t >> 4) + p * 16;
            int c4 = (t & 15) * 4;
            float4 v = *(const float4*)(W + o * 64 + c4);
            w_s[c4 + 0][o] = v.x; w_s[c4 + 1][o] = v.y;
            w_s[c4 + 2][o] = v.z; w_s[c4 + 3][o] = v.w;
        }
        __syncthreads();

        float acc[4][4] = {};
#pragma unroll 8
        for (int c = 0; c < 64; c++) {
            float4 w4 = *(float4*)&w_s[c][ty * 4];
            float4 h4 = *(float4*)&h_s[c][tx * 4];
            float wa[4] = {w4.x, w4.y, w4.z, w4.w};
            float ha[4] = {h4.x, h4.y, h4.z, h4.w};
#pragma unroll
            for (int ii = 0; ii < 4; ii++)
#pragma unroll
                for (int jj = 0; jj < 4; jj++)
                    acc[ii][jj] += wa[ii] * ha[jj];
        }
        float bias[4];
#pragma unroll
        for (int ii = 0; ii < 4; ii++) bias[ii] = Bv[ty * 4 + ii];

        float* out = ((mi == 0) ? g_q : (mi == 1) ? g_k : g_v)
                   + (size_t)(b * NN + n0) * 64;
#pragma unroll
        for (int jj = 0; jj < 4; jj++) {
            float4 r = make_float4(acc[0][jj] + bias[0], acc[1][jj] + bias[1],
                                   acc[2][jj] + bias[2], acc[3][jj] + bias[3]);
            *(float4*)(out + (tx * 4 + jj) * 64 + ty * 4) = r;
        }
    }
}

// ============================================================
// Kernel C: flash attention, tf32 tensor-core (mma.sync m16n8k8)
//   BM=128 queries/CTA, 8 warps x 16 rows, BN=64 keys/iter
// ============================================================
__global__ __launch_bounds__(256, 2) void flash_kernel()
{
    extern __shared__ float smem[];
    float* Ks = smem;                                  // [key][c]  stride 68
    float* Vs = smem + BN * KS_STRIDE;                 // [key][c]  stride 72
    float* Ps = smem + BN * KS_STRIDE + BN * VS_STRIDE;// [row][key] stride 68

    int b    = blockIdx.y;
    int n0q  = blockIdx.x * BM;
    int t    = threadIdx.x;
    int warp = t >> 5, lane = t & 31;
    int g    = lane >> 2, tig = lane & 3;
    int r0   = warp * 16;                              // warp's row block in CTA

    const float scale = 0.125f;                        // C^-0.5

    // ---- load Q fragments once (loop-invariant), scaled + tf32-rounded ----
    unsigned Qf[8][4];
    {
        const float* Qa = g_q + ((size_t)b * NN + n0q + r0 + g) * 64;
        const float* Qb = Qa + 8 * 64;                 // row g+8
#pragma unroll
        for (int k0 = 0; k0 < 8; k0++) {
            Qf[k0][0] = __float_as_uint(to_tf32(scale * Qa[8 * k0 + tig]));
            Qf[k0][1] = __float_as_uint(to_tf32(scale * Qb[8 * k0 + tig]));
            Qf[k0][2] = __float_as_uint(to_tf32(scale * Qa[8 * k0 + tig + 4]));
            Qf[k0][3] = __float_as_uint(to_tf32(scale * Qb[8 * k0 + tig + 4]));
        }
    }

    float m0 = -1e30f, m1 = -1e30f, l0 = 0.f, l1 = 0.f;
    float O[8][4];
#pragma unroll
    for (int n = 0; n < 8; n++)
#pragma unroll
        for (int j = 0; j < 4; j++) O[n][j] = 0.f;

    for (int kt = 0; kt < NKT; kt++) {
        int m0k = kt * BN;
        __syncthreads();   // prior iter done with Ks/Vs
        // ---- stage K,V tiles (coalesced, tf32-rounded) ----
#pragma unroll
        for (int p = 0; p < 2; p++) {
            int row  = (t >> 4) + p * 16;              // 0..31 (x2 halves below)
            int col4 = (t & 15) * 4;
#pragma unroll
            for (int h = 0; h < 2; h++) {
                int r = row + h * 32;
                float4 kv = *(const float4*)(g_k + ((size_t)b * NN + m0k + r) * 64 + col4);
                float4 vv = *(const float4*)(g_v + ((size_t)b * NN + m0k + r) * 64 + col4);
                Ks[r * KS_STRIDE + col4 + 0] = to_tf32(kv.x);
                Ks[r * KS_STRIDE + col4 + 1] = to_tf32(kv.y);
                Ks[r * KS_STRIDE + col4 + 2] = to_tf32(kv.z);
                Ks[r * KS_STRIDE + col4 + 3] = to_tf32(kv.w);
                Vs[r * VS_STRIDE + col4 + 0] = to_tf32(vv.x);
                Vs[r * VS_STRIDE + col4 + 1] = to_tf32(vv.y);
                Vs[r * VS_STRIDE + col4 + 2] = to_tf32(vv.z);
                Vs[r * VS_STRIDE + col4 + 3] = to_tf32(vv.w);
            }
        }
        __syncthreads();

        // ---- S = Q K^T  (16 x 64 per warp) ----
        float S[8][4];
#pragma unroll
        for (int n = 0; n < 8; n++)
#pragma unroll
            for (int j = 0; j < 4; j++) S[n][j] = 0.f;

#pragma unroll
        for (int k0 = 0; k0 < 8; k0++) {
#pragma unroll
            for (int n = 0; n < 8; n++) {
                unsigned b0 = __float_as_uint(Ks[(8 * n + g) * KS_STRIDE + 8 * k0 + tig]);
                unsigned b1 = __float_as_uint(Ks[(8 * n + g) * KS_STRIDE + 8 * k0 + tig + 4]);
                mma8(S[n], Qf[k0], b0, b1);
            }
        }

        // ---- online softmax (rows g and g+8 of this warp's block) ----
        float mx0 = -1e30f, mx1 = -1e30f;
#pragma unroll
        for (int n = 0; n < 8; n++) {
            mx0 = fmaxf(mx0, fmaxf(S[n][0], S[n][1]));
            mx1 = fmaxf(mx1, fmaxf(S[n][2], S[n][3]));
        }
        mx0 = fmaxf(mx0, __shfl_xor_sync(0xffffffffu, mx0, 1));
        mx0 = fmaxf(mx0, __shfl_xor_sync(0xffffffffu, mx0, 2));
        mx1 = fmaxf(mx1, __shfl_xor_sync(0xffffffffu, mx1, 1));
        mx1 = fmaxf(mx1, __shfl_xor_sync(0xffffffffu, mx1, 2));

        float mn0 = fmaxf(m0, mx0), mn1 = fmaxf(m1, mx1);
        float corr0 = __expf(m0 - mn0), corr1 = __expf(m1 - mn1);
        m0 = mn0; m1 = mn1;

        float rs0 = 0.f, rs1 = 0.f;
#pragma unroll
        for (int n = 0; n < 8; n++) {
            S[n][0] = __expf(S[n][0] - mn0);
            S[n][1] = __expf(S[n][1] - mn0);
            S[n][2] = __expf(S[n][2] - mn1);
            S[n][3] = __expf(S[n][3] - mn1);
            rs0 += S[n][0] + S[n][1];
            rs1 += S[n][2] + S[n][3];
        }
        rs0 += __shfl_xor_sync(0xffffffffu, rs0, 1);
        rs0 += __shfl_xor_sync(0xffffffffu, rs0, 2);
        rs1 += __shfl_xor_sync(0xffffffffu, rs1, 1);
        rs1 += __shfl_xor_sync(0xffffffffu, rs1, 2);
        l0 = l0 * corr0 + rs0;
        l1 = l1 * corr1 + rs1;

#pragma unroll
        for (int n = 0; n < 8; n++) {
            O[n][0] *= corr0; O[n][1] *= corr0;
            O[n][2] *= corr1; O[n][3] *= corr1;
        }

        // ---- stage P (per-warp rows; warp-local sync only) ----
        float* Pw0 = Ps + (r0 + g) * PS_STRIDE;
        float* Pw1 = Ps + (r0 + g + 8) * PS_STRIDE;
#pragma unroll
        for (int n = 0; n < 8; n++) {
            *(float2*)&Pw0[8 * n + 2 * tig] = make_float2(to_tf32(S[n][0]), to_tf32(S[n][1]));
            *(float2*)&Pw1[8 * n + 2 * tig] = make_float2(to_tf32(S[n][2]), to_tf32(S[n][3]));
        }
        __syncwarp();

        // ---- O += P V ----
#pragma unroll
        for (int k0 = 0; k0 < 8; k0++) {
            unsigned a[4];
            a[0] = __float_as_uint(Pw0[8 * k0 + tig]);
            a[1] = __float_as_uint(Pw1[8 * k0 + tig]);
            a[2] = __float_as_uint(Pw0[8 * k0 + tig + 4]);
            a[3] = __float_as_uint(Pw1[8 * k0 + tig + 4]);
#pragma unroll
            for (int n = 0; n < 8; n++) {
                unsigned b0 = __float_as_uint(Vs[(8 * k0 + tig) * VS_STRIDE + 8 * n + g]);
                unsigned b1 = __float_as_uint(Vs[(8 * k0 + tig + 4) * VS_STRIDE + 8 * n + g]);
                mma8(O[n], a, b0, b1);
            }
        }
        __syncwarp();   // Pw reads done before next iter's overwrite
    }

    // ---- epilogue ----
    float inv0 = 1.f / l0, inv1 = 1.f / l1;
    float* Oa = g_o + ((size_t)b * NN + n0q + r0 + g) * 64;
    float* Ob = Oa + 8 * 64;
#pragma unroll
    for (int n = 0; n < 8; n++) {
        *(float2*)&Oa[8 * n + 2 * tig] = make_float2(O[n][0] * inv0, O[n][1] * inv0);
        *(float2*)&Ob[8 * n + 2 * tig] = make_float2(O[n][2] * inv1, O[n][3] * inv1);
    }
}

// ============================================================
// Kernel D: output 1x1 conv + bias + residual
// ============================================================
__global__ __launch_bounds__(256) void proj_kernel(
    const float* __restrict__ x,
    const float* __restrict__ wo, const float* __restrict__ bo,
    float* __restrict__ out)
{
    __shared__ float A_s[64][68];   // [c][n]
    __shared__ float Wt[64][68];    // [c][o]
    int b  = blockIdx.y;
    int n0 = blockIdx.x * 64;
    int t  = threadIdx.x;
    int tx = t & 15, ty = t >> 4;

#pragma unroll
    for (int p = 0; p < 4; p++) {
        int i  = (t >> 4) + p * 16;
        int c4 = (t & 15) * 4;
        float4 v = *(const float4*)(g_o + (size_t)(b * NN + n0 + i) * 64 + c4);
        A_s[c4 + 0][i] = v.x; A_s[c4 + 1][i] = v.y;
        A_s[c4 + 2][i] = v.z; A_s[c4 + 3][i] = v.w;
        float4 w = *(const float4*)(wo + i * 64 + c4);
        Wt[c4 + 0][i] = w.x; Wt[c4 + 1][i] = w.y;
        Wt[c4 + 2][i] = w.z; Wt[c4 + 3][i] = w.w;
    }
    __syncthreads();

    float acc[4][4] = {};
#pragma unroll 8
    for (int c = 0; c < 64; c++) {
        float4 w4 = *(float4*)&Wt[c][ty * 4];
        float4 a4 = *(float4*)&A_s[c][tx * 4];
        float wa[4] = {w4.x, w4.y, w4.z, w4.w};
        float aa[4] = {a4.x, a4.y, a4.z, a4.w};
#pragma unroll
        for (int ii = 0; ii < 4; ii++)
#pragma unroll
            for (int jj = 0; jj < 4; jj++)
                acc[ii][jj] += wa[ii] * aa[jj];
    }

#pragma unroll
    for (int ii = 0; ii < 4; ii++) {
        int o = ty * 4 + ii;
        float bias = bo[o];
        const float4 xv = *(const float4*)(x + (size_t)(b * 64 + o) * NN + n0 + tx * 4);
        float4 r = make_float4(xv.x + bias + acc[ii][0], xv.y + bias + acc[ii][1],
                               xv.z + bias + acc[ii][2], xv.w + bias + acc[ii][3]);
        *(float4*)(out + (size_t)(b * 64 + o) * NN + n0 + tx * 4) = r;
    }
}

// ============================================================
extern "C" void kernel_launch(void* const* d_in, const int* in_sizes, int n_in,
                              void* d_out, int out_size)
{
    const float* x  = (const float*)d_in[0];
    const float* wq = (const float*)d_in[1];
    const float* bq = (const float*)d_in[2];
    const float* wk = (const float*)d_in[3];
    const float* bk = (const float*)d_in[4];
    const float* wv = (const float*)d_in[5];
    const float* bv = (const float*)d_in[6];
    const float* wo = (const float*)d_in[7];
    const float* bo = (const float*)d_in[8];
    float* out = (float*)d_out;

    cudaFuncSetAttribute(flash_kernel, cudaFuncAttributeMaxDynamicSharedMemorySize,
                         SMEM_FLASH);

    norm_stats<<<BB * CC, 256>>>(x);
    qkv_kernel<<<dim3(NN / 64, BB), 256>>>(x, wq, bq, wk, bk, wv, bv);
    flash_kernel<<<dim3(NQB, BB), 256, SMEM_FLASH>>>();
    proj_kernel<<<dim3(NN / 64, BB), 256>>>(x, wo, bo, out);
}